// round 4
// baseline (speedup 1.0000x reference)
#include <cuda_runtime.h>
#include <math.h>

// sLSTM cell, fused: 8 GEMMs (x@W_g + h@U_g, g in {i,f,o,z}) + biases +
// gate nonlinearities + cell update, all in ONE kernel launch.
//
// Shapes: B=4096, D_IN=D_H=2048.
// Each block computes a 64(M) x 64(N) tile of ALL FOUR gate pre-activations
// (sharing the A tile across gates for 4x A-reuse), then does the elementwise
// epilogue in registers and writes h, c, n (concatenated in d_out).

#define BB 4096
#define DD 2048
#define TM 64
#define TN 64
#define TK 16
#define BD (BB * DD)   // 8388608 elements per output tensor

__global__ __launch_bounds__(256, 2)
void slstm_fused_kernel(
    const float* __restrict__ x,     const float* __restrict__ hprev,
    const float* __restrict__ cprev, const float* __restrict__ nprev,
    const float* __restrict__ Wi, const float* __restrict__ bi, const float* __restrict__ Ui,
    const float* __restrict__ Wf, const float* __restrict__ bf, const float* __restrict__ Uf,
    const float* __restrict__ Wo, const float* __restrict__ bo, const float* __restrict__ Uo,
    const float* __restrict__ Wz, const float* __restrict__ bz, const float* __restrict__ Uz,
    float* __restrict__ out)
{
    __shared__ float As[TK][TM];        // A tile, transposed (k-major)
    __shared__ float Bs[4][TK][TN];     // one B tile per gate

    const int tid = threadIdx.x;        // 256 threads = 16x16
    const int ty  = tid >> 4;           // 0..15 -> 4 M-rows each
    const int tx  = tid & 15;           // 0..15 -> 4 N-cols each
    const int m0  = blockIdx.y * TM;
    const int j0  = blockIdx.x * TN;

    // Loader indices
    const int ar = tid >> 2;            // 0..63  (M row within tile)
    const int ac = (tid & 3) * 4;       // 0,4,8,12 (k offset, float4)
    const int br = tid >> 4;            // 0..15  (k row within tile)
    const int bc = (tid & 15) * 4;      // 0..60  (j offset, float4)

    float acc[4][4][4];
    #pragma unroll
    for (int g = 0; g < 4; ++g)
        #pragma unroll
        for (int im = 0; im < 4; ++im)
            #pragma unroll
            for (int jj = 0; jj < 4; ++jj)
                acc[g][im][jj] = 0.0f;

    // Phase 0: A = x,      B = W_g   (K = 2048)
    // Phase 1: A = h_prev, B = U_g   (K = 2048)
    #pragma unroll 1
    for (int ph = 0; ph < 2; ++ph) {
        const float* Ag  = ph ? hprev : x;
        const float* Bm0 = ph ? Ui : Wi;
        const float* Bm1 = ph ? Uf : Wf;
        const float* Bm2 = ph ? Uo : Wo;
        const float* Bm3 = ph ? Uz : Wz;

        #pragma unroll 1
        for (int k0 = 0; k0 < DD; k0 += TK) {
            __syncthreads();   // previous compute done before overwrite

            // Load A tile (64 x 16), store transposed
            float4 av = *(const float4*)&Ag[(size_t)(m0 + ar) * DD + k0 + ac];
            As[ac + 0][ar] = av.x;
            As[ac + 1][ar] = av.y;
            As[ac + 2][ar] = av.z;
            As[ac + 3][ar] = av.w;

            // Load 4 B tiles (16 x 64 each), k-major direct
            *(float4*)&Bs[0][br][bc] = *(const float4*)&Bm0[(size_t)(k0 + br) * DD + j0 + bc];
            *(float4*)&Bs[1][br][bc] = *(const float4*)&Bm1[(size_t)(k0 + br) * DD + j0 + bc];
            *(float4*)&Bs[2][br][bc] = *(const float4*)&Bm2[(size_t)(k0 + br) * DD + j0 + bc];
            *(float4*)&Bs[3][br][bc] = *(const float4*)&Bm3[(size_t)(k0 + br) * DD + j0 + bc];

            __syncthreads();

            #pragma unroll
            for (int kk = 0; kk < TK; ++kk) {
                float a[4];
                *(float4*)a = *(const float4*)&As[kk][ty * 4];
                #pragma unroll
                for (int g = 0; g < 4; ++g) {
                    float b[4];
                    *(float4*)b = *(const float4*)&Bs[g][kk][tx * 4];
                    #pragma unroll
                    for (int im = 0; im < 4; ++im)
                        #pragma unroll
                        for (int jj = 0; jj < 4; ++jj)
                            acc[g][im][jj] = fmaf(a[im], b[jj], acc[g][im][jj]);
                }
            }
        }
    }

    // ---- Epilogue: biases + nonlinearities + cell update ----
    float bib[4], bfb[4], bob[4], bzb[4];
    #pragma unroll
    for (int jj = 0; jj < 4; ++jj) {
        int j = j0 + tx * 4 + jj;
        bib[jj] = bi[j];
        bfb[jj] = bf[j];
        bob[jj] = bo[j];
        bzb[jj] = bz[j];
    }

    #pragma unroll
    for (int im = 0; im < 4; ++im) {
        const int m = m0 + ty * 4 + im;
        #pragma unroll
        for (int jj = 0; jj < 4; ++jj) {
            const int j = j0 + tx * 4 + jj;
            const size_t idx = (size_t)m * DD + j;

            float pi = acc[0][im][jj] + bib[jj];
            float pf = acc[1][im][jj] + bfb[jj];
            float po = acc[2][im][jj] + bob[jj];
            float pz = acc[3][im][jj] + bzb[jj];

            float ig = expf(pi);
            float fg = expf(pf);
            float og = 1.0f / (1.0f + expf(-po));
            float zg = tanhf(pz);

            float cv = fg * cprev[idx] + ig * zg;
            float nv = fg * nprev[idx] + ig;
            float hv = og * (cv / (nv + 1e-6f));

            out[idx]            = hv;   // h
            out[BD + idx]       = cv;   // c
            out[2 * (size_t)BD + idx] = nv;   // n
        }
    }
}

extern "C" void kernel_launch(void* const* d_in, const int* in_sizes, int n_in,
                              void* d_out, int out_size)
{
    const float* x     = (const float*)d_in[0];
    const float* hprev = (const float*)d_in[1];
    const float* cprev = (const float*)d_in[2];
    const float* nprev = (const float*)d_in[3];
    const float* Wi = (const float*)d_in[4];
    const float* bi = (const float*)d_in[5];
    const float* Ui = (const float*)d_in[6];
    const float* Wf = (const float*)d_in[7];
    const float* bf = (const float*)d_in[8];
    const float* Uf = (const float*)d_in[9];
    const float* Wo = (const float*)d_in[10];
    const float* bo = (const float*)d_in[11];
    const float* Uo = (const float*)d_in[12];
    const float* Wz = (const float*)d_in[13];
    const float* bz = (const float*)d_in[14];
    const float* Uz = (const float*)d_in[15];
    float* out = (float*)d_out;

    dim3 grid(DD / TN, BB / TM);   // (32, 64)
    dim3 block(256);
    slstm_fused_kernel<<<grid, block>>>(
        x, hprev, cprev, nprev,
        Wi, bi, Ui, Wf, bf, Uf, Wo, bo, Uo, Wz, bz, Uz,
        out);
}

// round 6
// speedup vs baseline: 1.6089x; 1.6089x over previous
#include <cuda_runtime.h>
#include <cuda_bf16.h>
#include <cstdint>

#define BB 4096
#define DD 2048
#define BD (BB * DD)

// ---------------- device scratch ----------------
// A: [phase(2)][4096][2048] bf16 row-major (K contiguous)
__device__ __nv_bfloat16 g_Ahi[2ull * BB * DD];
__device__ __nv_bfloat16 g_Alo[2ull * BB * DD];
// B: [gate*2+phase(8)][N=2048][K=2048] bf16 row-major (transposed W/U)
__device__ __nv_bfloat16 g_Bhi[8ull * DD * DD];
__device__ __nv_bfloat16 g_Blo[8ull * DD * DD];
// Pre-activations: [gate(4)][4096][2048] fp32
__device__ float g_P[4ull * BD];

__device__ __forceinline__ uint32_t smem_u32(const void* p) {
    uint32_t a;
    asm("{ .reg .u64 t; cvta.to.shared.u64 t, %1; cvt.u32.u64 %0, t; }" : "=r"(a) : "l"(p));
    return a;
}
__device__ __forceinline__ uint32_t pk2(float a, float b) {
    uint16_t ua = __bfloat16_as_ushort(__float2bfloat16(a));
    uint16_t ub = __bfloat16_as_ushort(__float2bfloat16(b));
    return (uint32_t)ua | ((uint32_t)ub << 16);
}

// ---------------- Pack A: x / h_prev -> hi/lo bf16 --------------------------
__global__ __launch_bounds__(256) void pack_a_kernel(
    const float* __restrict__ x, const float* __restrict__ h)
{
    uint32_t i = blockIdx.x * 256u + threadIdx.x;   // 2*4096*512 threads
    uint32_t k4 = i & 511u;
    uint32_t rest = i >> 9;
    uint32_t mm = rest & 4095u;
    uint32_t p = rest >> 12;
    const float* src = p ? h : x;
    uint32_t k = k4 * 4;
    float4 v = *(const float4*)&src[(size_t)mm * DD + k];

    float h0 = __bfloat162float(__float2bfloat16(v.x));
    float h1 = __bfloat162float(__float2bfloat16(v.y));
    float h2 = __bfloat162float(__float2bfloat16(v.z));
    float h3 = __bfloat162float(__float2bfloat16(v.w));
    unsigned long long phi = (unsigned long long)pk2(v.x, v.y) |
                             ((unsigned long long)pk2(v.z, v.w) << 32);
    unsigned long long plo = (unsigned long long)pk2(v.x - h0, v.y - h1) |
                             ((unsigned long long)pk2(v.z - h2, v.w - h3) << 32);

    size_t o = ((size_t)p * BB + mm) * DD + k;
    *(unsigned long long*)&g_Ahi[o] = phi;
    *(unsigned long long*)&g_Alo[o] = plo;
}

// ---------------- Pack B: transpose W/U -> [N][K] hi/lo bf16 ----------------
__global__ __launch_bounds__(256) void pack_b_kernel(
    const float* __restrict__ W0, const float* __restrict__ W1,
    const float* __restrict__ W2, const float* __restrict__ W3,
    const float* __restrict__ W4, const float* __restrict__ W5,
    const float* __restrict__ W6, const float* __restrict__ W7)
{
    __shared__ float s[64][65];
    const float* mats[8] = {W0, W1, W2, W3, W4, W5, W6, W7};
    const int gp = blockIdx.z;            // gate*2 + phase
    const float* src = mats[gp];
    const int kb = blockIdx.x, nb = blockIdx.y;
    const int t = threadIdx.x;

    const int cn = (t & 15) * 4;          // n offset
    const int r0 = t >> 4;                // k offset
    #pragma unroll
    for (int pass = 0; pass < 4; ++pass) {
        int r = pass * 16 + r0;
        float4 v = *(const float4*)&src[(size_t)(kb * 64 + r) * DD + nb * 64 + cn];
        s[r][cn] = v.x; s[r][cn + 1] = v.y; s[r][cn + 2] = v.z; s[r][cn + 3] = v.w;
    }
    __syncthreads();

    const int orow = t >> 2;              // n local (0..63)
    const int kbase = (t & 3) * 16;       // k local start
    size_t base = (size_t)gp * DD * DD + (size_t)(nb * 64 + orow) * DD + kb * 64;
    #pragma unroll
    for (int u = 0; u < 4; ++u) {
        int kl = kbase + u * 4;
        float v0 = s[kl][orow], v1 = s[kl + 1][orow];
        float v2 = s[kl + 2][orow], v3 = s[kl + 3][orow];
        float h0 = __bfloat162float(__float2bfloat16(v0));
        float h1 = __bfloat162float(__float2bfloat16(v1));
        float h2 = __bfloat162float(__float2bfloat16(v2));
        float h3 = __bfloat162float(__float2bfloat16(v3));
        unsigned long long phi = (unsigned long long)pk2(v0, v1) |
                                 ((unsigned long long)pk2(v2, v3) << 32);
        unsigned long long plo = (unsigned long long)pk2(v0 - h0, v1 - h1) |
                                 ((unsigned long long)pk2(v2 - h2, v3 - h3) << 32);
        *(unsigned long long*)&g_Bhi[base + kl] = phi;
        *(unsigned long long*)&g_Blo[base + kl] = plo;
    }
}

// ---------------- bf16 mma.sync GEMM (split-bf16, 3 combos x 2 phases) ------
#define BM 128
#define BN 128
#define BKT 64
#define NITERS 192            // 6 segments * 32 iters (BK=64 over K=2048)
#define STAGE_BYTES 32768     // A 16KB + B 16KB
#define SMEM_TOTAL (3 * STAGE_BYTES)

__device__ __forceinline__ uint32_t sw_off(uint32_t row, uint32_t chunk) {
    return row * 128u + ((chunk ^ (row & 7u)) << 4);
}
__device__ __forceinline__ void cp16(uint32_t saddr, const void* gaddr) {
    asm volatile("cp.async.cg.shared.global [%0], [%1], 16;" :: "r"(saddr), "l"(gaddr));
}

struct SegTab { const __nv_bfloat16* A[6]; const __nv_bfloat16* B[6]; };

__device__ __forceinline__ void gemm_issue(
    const SegTab& st, int t, int stage, uint32_t sb,
    int m0, int n0, uint32_t lrow, uint32_t lcb)
{
    const int seg = t >> 5;
    const int k0 = (t & 31) * BKT;
    const __nv_bfloat16* Ag = st.A[seg] + (size_t)(m0 + lrow) * DD + k0;
    const __nv_bfloat16* Bg = st.B[seg] + (size_t)(n0 + lrow) * DD + k0;
    const uint32_t sA = sb + stage * STAGE_BYTES;
    const uint32_t sB = sA + 16384;
    #pragma unroll
    for (int c = 0; c < 4; ++c) {
        uint32_t ch = lcb + c;
        cp16(sA + sw_off(lrow, ch), Ag + ch * 8);
        cp16(sB + sw_off(lrow, ch), Bg + ch * 8);
    }
}

__global__ __launch_bounds__(256, 1) void slstm_gemm(float* __restrict__ P)
{
    extern __shared__ char smem[];
    const uint32_t sb = smem_u32(smem);
    const int tid = threadIdx.x;
    const int lane = tid & 31;
    const int wid = tid >> 5;
    const int m0 = blockIdx.x * BM;
    const int n0 = blockIdx.y * BN;
    const int g  = blockIdx.z;
    const int wm = (wid & 1) * 64;        // warp M origin within tile
    const int wn = (wid >> 1) * 32;       // warp N origin within tile

    SegTab st;
    {
        const __nv_bfloat16* Ah0 = g_Ahi;
        const __nv_bfloat16* Al0 = g_Alo;
        const __nv_bfloat16* Ah1 = g_Ahi + (size_t)BB * DD;
        const __nv_bfloat16* Al1 = g_Alo + (size_t)BB * DD;
        const __nv_bfloat16* Bh0 = g_Bhi + (size_t)(g * 2 + 0) * DD * DD;
        const __nv_bfloat16* Bl0 = g_Blo + (size_t)(g * 2 + 0) * DD * DD;
        const __nv_bfloat16* Bh1 = g_Bhi + (size_t)(g * 2 + 1) * DD * DD;
        const __nv_bfloat16* Bl1 = g_Blo + (size_t)(g * 2 + 1) * DD * DD;
        st.A[0] = Ah0; st.B[0] = Bh0;     // hi*hi   phase 0
        st.A[1] = Al0; st.B[1] = Bh0;     // lo*hi
        st.A[2] = Ah0; st.B[2] = Bl0;     // hi*lo
        st.A[3] = Ah1; st.B[3] = Bh1;     // phase 1
        st.A[4] = Al1; st.B[4] = Bh1;
        st.A[5] = Ah1; st.B[5] = Bl1;
    }

    const uint32_t lrow = tid >> 1;        // 0..127
    const uint32_t lcb  = (tid & 1) * 4;   // chunk base 0 or 4

    float d[4][4][4];
    #pragma unroll
    for (int mi = 0; mi < 4; ++mi)
        #pragma unroll
        for (int nj = 0; nj < 4; ++nj)
            #pragma unroll
            for (int e = 0; e < 4; ++e) d[mi][nj][e] = 0.0f;

    // prologue: 2 stages in flight
    gemm_issue(st, 0, 0, sb, m0, n0, lrow, lcb);
    asm volatile("cp.async.commit_group;" ::: "memory");
    gemm_issue(st, 1, 1, sb, m0, n0, lrow, lcb);
    asm volatile("cp.async.commit_group;" ::: "memory");

    #pragma unroll 1
    for (int t = 0; t < NITERS; ++t) {
        asm volatile("cp.async.wait_group 1;" ::: "memory");
        __syncthreads();

        const int stage = t % 3;
        const uint32_t sA = sb + stage * STAGE_BYTES;
        const uint32_t sB = sA + 16384;

        #pragma unroll
        for (int ks = 0; ks < 4; ++ks) {
            uint32_t a[4][4];
            #pragma unroll
            for (int mi = 0; mi < 4; ++mi) {
                uint32_t row = wm + mi * 16 + (lane & 15);
                uint32_t ch  = ks * 2 + (lane >> 4);
                uint32_t ad = sA + sw_off(row, ch);
                asm volatile("ldmatrix.sync.aligned.m8n8.x4.shared.b16 {%0,%1,%2,%3}, [%4];"
                             : "=r"(a[mi][0]), "=r"(a[mi][1]), "=r"(a[mi][2]), "=r"(a[mi][3])
                             : "r"(ad));
            }
            uint32_t b[2][4];
            #pragma unroll
            for (int n2 = 0; n2 < 2; ++n2) {
                uint32_t row = wn + n2 * 16 + (lane & 7) + ((lane >> 4) << 3);
                uint32_t ch  = ks * 2 + ((lane >> 3) & 1);
                uint32_t ad = sB + sw_off(row, ch);
                asm volatile("ldmatrix.sync.aligned.m8n8.x4.shared.b16 {%0,%1,%2,%3}, [%4];"
                             : "=r"(b[n2][0]), "=r"(b[n2][1]), "=r"(b[n2][2]), "=r"(b[n2][3])
                             : "r"(ad));
            }
            #pragma unroll
            for (int mi = 0; mi < 4; ++mi) {
                #pragma unroll
                for (int nj = 0; nj < 4; ++nj) {
                    uint32_t b0 = b[nj >> 1][(nj & 1) * 2];
                    uint32_t b1 = b[nj >> 1][(nj & 1) * 2 + 1];
                    asm volatile(
                        "mma.sync.aligned.m16n8k16.row.col.f32.bf16.bf16.f32 "
                        "{%0,%1,%2,%3}, {%4,%5,%6,%7}, {%8,%9}, {%0,%1,%2,%3};"
                        : "+f"(d[mi][nj][0]), "+f"(d[mi][nj][1]),
                          "+f"(d[mi][nj][2]), "+f"(d[mi][nj][3])
                        : "r"(a[mi][0]), "r"(a[mi][1]), "r"(a[mi][2]), "r"(a[mi][3]),
                          "r"(b0), "r"(b1));
                }
            }
        }

        __syncthreads();
        if (t + 2 < NITERS)
            gemm_issue(st, t + 2, (t + 2) % 3, sb, m0, n0, lrow, lcb);
        asm volatile("cp.async.commit_group;" ::: "memory");
    }

    // write pre-activations to scratch
    float* Pg = P + (size_t)g * BD;
    #pragma unroll
    for (int mi = 0; mi < 4; ++mi) {
        #pragma unroll
        for (int nj = 0; nj < 4; ++nj) {
            int r = m0 + wm + mi * 16 + (lane >> 2);
            int c = n0 + wn + nj * 8 + (lane & 3) * 2;
            float2 v0 = {d[mi][nj][0], d[mi][nj][1]};
            float2 v1 = {d[mi][nj][2], d[mi][nj][3]};
            *(float2*)&Pg[(size_t)r * DD + c]       = v0;
            *(float2*)&Pg[(size_t)(r + 8) * DD + c] = v1;
        }
    }
}

// ---------------- fused sLSTM epilogue (bandwidth-bound) --------------------
__global__ __launch_bounds__(256) void slstm_epi(
    const float* __restrict__ cprev, const float* __restrict__ nprev,
    const float* __restrict__ bI, const float* __restrict__ bF,
    const float* __restrict__ bO, const float* __restrict__ bZ,
    float* __restrict__ out)
{
    size_t i = ((size_t)blockIdx.x * 256 + threadIdx.x) * 4;
    int j = (int)(i & 2047u);

    float4 pi4 = *(const float4*)&g_P[i];
    float4 pf4 = *(const float4*)&g_P[(size_t)BD + i];
    float4 po4 = *(const float4*)&g_P[2 * (size_t)BD + i];
    float4 pz4 = *(const float4*)&g_P[3 * (size_t)BD + i];
    float4 bi4 = *(const float4*)&bI[j];
    float4 bf4 = *(const float4*)&bF[j];
    float4 bo4 = *(const float4*)&bO[j];
    float4 bz4 = *(const float4*)&bZ[j];
    float4 cp4 = *(const float4*)&cprev[i];
    float4 np4 = *(const float4*)&nprev[i];

    float pi[4] = {pi4.x + bi4.x, pi4.y + bi4.y, pi4.z + bi4.z, pi4.w + bi4.w};
    float pf[4] = {pf4.x + bf4.x, pf4.y + bf4.y, pf4.z + bf4.z, pf4.w + bf4.w};
    float po[4] = {po4.x + bo4.x, po4.y + bo4.y, po4.z + bo4.z, po4.w + bo4.w};
    float pz[4] = {pz4.x + bz4.x, pz4.y + bz4.y, pz4.z + bz4.z, pz4.w + bz4.w};
    float cp[4] = {cp4.x, cp4.y, cp4.z, cp4.w};
    float np[4] = {np4.x, np4.y, np4.z, np4.w};

    float hv[4], cv[4], nv[4];
    #pragma unroll
    for (int e = 0; e < 4; ++e) {
        float ig = __expf(pi[e]);
        float fg = __expf(pf[e]);
        float og = 1.0f / (1.0f + __expf(-po[e]));
        float zg = tanhf(pz[e]);
        float cc = fg * cp[e] + ig * zg;
        float nn = fg * np[e] + ig;
        cv[e] = cc; nv[e] = nn;
        hv[e] = og * (cc / (nn + 1e-6f));
    }
    *(float4*)&out[i]                   = *(float4*)hv;
    *(float4*)&out[(size_t)BD + i]      = *(float4*)cv;
    *(float4*)&out[2 * (size_t)BD + i]  = *(float4*)nv;
}

// ---------------- launch -----------------------------------------------------
extern "C" void kernel_launch(void* const* d_in, const int* in_sizes, int n_in,
                              void* d_out, int out_size)
{
    const float* x     = (const float*)d_in[0];
    const float* hprev = (const float*)d_in[1];
    const float* cprev = (const float*)d_in[2];
    const float* nprev = (const float*)d_in[3];
    const float* Wi = (const float*)d_in[4];
    const float* bi = (const float*)d_in[5];
    const float* Ui = (const float*)d_in[6];
    const float* Wf = (const float*)d_in[7];
    const float* bf_ = (const float*)d_in[8];
    const float* Uf = (const float*)d_in[9];
    const float* Wo = (const float*)d_in[10];
    const float* bo = (const float*)d_in[11];
    const float* Uo = (const float*)d_in[12];
    const float* Wz = (const float*)d_in[13];
    const float* bz = (const float*)d_in[14];
    const float* Uz = (const float*)d_in[15];
    float* out = (float*)d_out;

    cudaFuncSetAttribute(slstm_gemm,
                         cudaFuncAttributeMaxDynamicSharedMemorySize, SMEM_TOTAL);

    float* Pptr = nullptr;
    cudaGetSymbolAddress((void**)&Pptr, g_P);

    pack_a_kernel<<<16384, 256>>>(x, hprev);
    pack_b_kernel<<<dim3(32, 32, 8), 256>>>(Wi, Ui, Wf, Uf, Wo, Uo, Wz, Uz);
    slstm_gemm<<<dim3(BB / BM, DD / BN, 4), 256, SMEM_TOTAL>>>(Pptr);
    slstm_epi<<<BD / 4 / 256, 256>>>(cprev, nprev, bi, bf_, bo, bz, out);
}